// round 14
// baseline (speedup 1.0000x reference)
#include <cuda_runtime.h>

// Problem constants (fixed shapes from reference):
//   outputs1/2, input1/2 : [64,3,256,256] f32  -> NEL = 12,582,912 each
//   z1/z2                : [64,64,16,16]  f32  -> [64, 16384] flattened
#define BZ 64
#define DZ 16384
#define NEL 12582912
#define N4 (NEL / 4)

#define NCTR_BLOCKS 64          // contrastive blocks, each owns a 256-wide D slice
#define NMSE_BLOCKS 512         // 512 * 256 * 24 == N4 exactly; 576 total <= 592 -> one wave
#define MSE_ITERS 24
#define TOTAL_BLOCKS (NCTR_BLOCKS + NMSE_BLOCKS)

// Deterministic scratch (no atomics, every slot rewritten every launch)
__device__ float  g_crossp[NCTR_BLOCKS * 64 * 64];  // per-block partial cross[m][n]
__device__ float  g_cross[64 * 64];                 // fully reduced cross matrix
__device__ float  g_sq[128];                        // row sums of squares (z1: 0..63, z2: 64..127)
__device__ double g_msep[NMSE_BLOCKS];              // per-block MSE partial sums
__device__ double g_mse_total;                      // fully reduced MSE sum

__global__ __launch_bounds__(256)
void fused_kernel(const float* __restrict__ o1, const float* __restrict__ z1,
                  const float* __restrict__ o2, const float* __restrict__ z2,
                  const float* __restrict__ i1, const float* __restrict__ i2)
{
    const int tid = threadIdx.x;
    const int b   = blockIdx.x;

    if (b < NCTR_BLOCKS) {
        // ---------- contrastive cross-matrix partial: D slice [b*256, b*256+256) ----------
        // Shared tiles stored k-major: s[k][row], row padded to 68 (68*4 = 272 = 17*16,
        // so &s[k][4*t] stays 16B aligned for LDS.128 on the compute side).
        __shared__ __align__(16) float s1[32][68];
        __shared__ __align__(16) float s2[32][68];

        float acc[4][4];
#pragma unroll
        for (int i = 0; i < 4; ++i)
#pragma unroll
            for (int j = 0; j < 4; ++j) acc[i][j] = 0.0f;

        const int tx = tid & 15;   // n-tile coordinate
        const int ty = tid >> 4;   // m-tile coordinate
        const int c0 = b * 256;

        for (int t = 0; t < 8; ++t) {          // 8 k-tiles of 32
            const int ck = c0 + t * 32;
            __syncthreads();
            // load 64 rows x 32 k each tensor: 512 float4 per tensor, 2 per thread
#pragma unroll
            for (int i = 0; i < 2; ++i) {
                const int idx = tid + i * 256;      // 0..511
                const int r   = idx >> 3;           // row 0..63
                const int kk  = (idx & 7) * 4;      // k within tile
                float4 v1 = *(const float4*)(z1 + r * DZ + ck + kk);
                float4 v2 = *(const float4*)(z2 + r * DZ + ck + kk);
                s1[kk + 0][r] = v1.x; s1[kk + 1][r] = v1.y;
                s1[kk + 2][r] = v1.z; s1[kk + 3][r] = v1.w;
                s2[kk + 0][r] = v2.x; s2[kk + 1][r] = v2.y;
                s2[kk + 2][r] = v2.z; s2[kk + 3][r] = v2.w;
            }
            __syncthreads();
#pragma unroll
            for (int k = 0; k < 32; ++k) {
                const float4 av = *(const float4*)&s1[k][ty * 4];
                const float4 bv = *(const float4*)&s2[k][tx * 4];
                const float a[4] = {av.x, av.y, av.z, av.w};
                const float c[4] = {bv.x, bv.y, bv.z, bv.w};
#pragma unroll
                for (int i = 0; i < 4; ++i)
#pragma unroll
                    for (int j = 0; j < 4; ++j) acc[i][j] += a[i] * c[j];
            }
        }

        float* outp = g_crossp + b * 4096;
#pragma unroll
        for (int i = 0; i < 4; ++i)
#pragma unroll
            for (int j = 0; j < 4; ++j)
                outp[(ty * 4 + i) * 64 + (tx * 4 + j)] = acc[i][j];
    } else {
        // ---------- MSE: fixed 24 iters; pair 2 block-staggered by half the array ----------
        // Block mb reads pair 1 at chunk mb and pair 2 at chunk (mb+256)&511, so the
        // four 2MB-aligned streams never hit the same L2-slice/channel phase together.
        const int mb    = b - NCTR_BLOCKS;
        const int mb2   = (mb + 256) & 511;
        const int base  = mb  * (MSE_ITERS * 256) + tid;
        const int base2 = mb2 * (MSE_ITERS * 256) + tid;
        const float4* a1 = (const float4*)o1;
        const float4* c1 = (const float4*)i1;
        const float4* a2 = (const float4*)o2;
        const float4* c2 = (const float4*)i2;
        float s0 = 0.0f, s1s = 0.0f;
#pragma unroll
        for (int it = 0; it < MSE_ITERS; it += 2) {
            const int i0  = base  + it * 256;
            const int i1i = i0 + 256;
            const int j0  = base2 + it * 256;
            const int j1  = j0 + 256;
            const float4 xa = __ldcs(a1 + i0);
            const float4 ya = __ldcs(c1 + i0);
            const float4 xb = __ldcs(a2 + j0);
            const float4 yb = __ldcs(c2 + j0);
            const float4 xc = __ldcs(a1 + i1i);
            const float4 yc = __ldcs(c1 + i1i);
            const float4 xd = __ldcs(a2 + j1);
            const float4 yd = __ldcs(c2 + j1);
            float dx, dy, dz, dw;
            dx = xa.x - ya.x; dy = xa.y - ya.y; dz = xa.z - ya.z; dw = xa.w - ya.w;
            s0 += dx * dx + dy * dy + dz * dz + dw * dw;
            dx = xb.x - yb.x; dy = xb.y - yb.y; dz = xb.z - yb.z; dw = xb.w - yb.w;
            s0 += dx * dx + dy * dy + dz * dz + dw * dw;
            dx = xc.x - yc.x; dy = xc.y - yc.y; dz = xc.z - yc.z; dw = xc.w - yc.w;
            s1s += dx * dx + dy * dy + dz * dz + dw * dw;
            dx = xd.x - yd.x; dy = xd.y - yd.y; dz = xd.z - yd.z; dw = xd.w - yd.w;
            s1s += dx * dx + dy * dy + dz * dz + dw * dw;
        }
        float sum = s0 + s1s;
        __shared__ float red[8];
#pragma unroll
        for (int off = 16; off; off >>= 1) sum += __shfl_down_sync(0xffffffffu, sum, off);
        if ((tid & 31) == 0) red[tid >> 5] = sum;
        __syncthreads();
        if (tid < 32) {
            float v = (tid < 8) ? red[tid] : 0.0f;
#pragma unroll
            for (int off = 4; off; off >>= 1) v += __shfl_down_sync(0xffffffffu, v, off);
            if (tid == 0) g_msep[mb] = (double)v;
        }
    }
}

// Blocks 0..63: reduce cross row m over the 64 partials AND compute row-m sum of
// squares for z1/z2 (streamed here, where blocks are latency-bound and BW is idle).
// Block 64: reduce the MSE partials.
__global__ __launch_bounds__(256)
void rowreduce_kernel(const float* __restrict__ z1, const float* __restrict__ z2)
{
    const int tid = threadIdx.x;

    if (blockIdx.x == 64) {
        __shared__ double mred[8];
        double msum = 0.0;
#pragma unroll
        for (int i = tid; i < NMSE_BLOCKS; i += 256) msum += g_msep[i];
#pragma unroll
        for (int o = 16; o; o >>= 1) msum += __shfl_down_sync(0xffffffffu, msum, o);
        if ((tid & 31) == 0) mred[tid >> 5] = msum;
        __syncthreads();
        if (tid == 0) {
            double t = 0.0;
#pragma unroll
            for (int i = 0; i < 8; ++i) t += mred[i];
            g_mse_total = t;
        }
        return;
    }

    const int m = blockIdx.x;

    // ---- sum of squares for row m of z1 and z2 (4096 float4 each, 16/thread) ----
    const float4* zr1 = (const float4*)(z1 + m * DZ);
    const float4* zr2 = (const float4*)(z2 + m * DZ);
    float sq1 = 0.0f, sq2 = 0.0f;
#pragma unroll 4
    for (int i = tid; i < 4096; i += 256) {
        const float4 v1 = zr1[i];
        const float4 v2 = zr2[i];
        sq1 += v1.x * v1.x + v1.y * v1.y + v1.z * v1.z + v1.w * v1.w;
        sq2 += v2.x * v2.x + v2.y * v2.y + v2.z * v2.z + v2.w * v2.w;
    }

    // ---- reduce cross row m over the 64 partials ----
    const int n = tid & 63;       // output column
    const int q = tid >> 6;       // partial group 0..3 (16 partials each)
    float s = 0.0f;
#pragma unroll
    for (int j = 0; j < 16; ++j)
        s += g_crossp[(q * 16 + j) * 4096 + m * 64 + n];

    __shared__ float sm[4][64];
    __shared__ float sqred[2][8];
    sm[q][n] = s;

    // block-reduce the two sq scalars
#pragma unroll
    for (int o = 16; o; o >>= 1) {
        sq1 += __shfl_down_sync(0xffffffffu, sq1, o);
        sq2 += __shfl_down_sync(0xffffffffu, sq2, o);
    }
    if ((tid & 31) == 0) { sqred[0][tid >> 5] = sq1; sqred[1][tid >> 5] = sq2; }
    __syncthreads();

    if (tid < 64)
        g_cross[m * 64 + tid] = sm[0][tid] + sm[1][tid] + sm[2][tid] + sm[3][tid];
    if (tid == 0) {
        float t1 = 0.0f, t2 = 0.0f;
#pragma unroll
        for (int i = 0; i < 8; ++i) { t1 += sqred[0][i]; t2 += sqred[1][i]; }
        g_sq[m]      = t1;
        g_sq[64 + m] = t2;
    }
}

// One block: apply margins over the reduced 64x64 matrix and combine everything.
__global__ __launch_bounds__(256)
void finalize_kernel(float* __restrict__ out)
{
    const int tid = threadIdx.x;
    __shared__ float ssq[128];
    __shared__ double sred[2][8];

    if (tid < 128) ssq[tid] = g_sq[tid];
    __syncthreads();

    // thread tid owns entries [tid*16, tid*16+16): m = tid>>2, n = (tid&3)*16 + 0..15
    const int m  = tid >> 2;
    const int n0 = (tid & 3) * 16;
    const float4* cp = (const float4*)(g_cross + m * 64 + n0);
    double lp = 0.0, ln = 0.0;
#pragma unroll
    for (int k = 0; k < 4; ++k) {
        const float4 cv = cp[k];
        const float cr[4] = {cv.x, cv.y, cv.z, cv.w};
#pragma unroll
        for (int j = 0; j < 4; ++j) {
            const int n = n0 + k * 4 + j;
            const double d = ((double)ssq[m] + (double)ssq[64 + n] - 2.0 * (double)cr[j])
                             * (1.0 / (double)DZ);
            if (m == n) {
                if (d > 0.01) lp += d - 0.01;
            } else if (d < 0.4) {
                ln += 0.4 - d;
            }
        }
    }

#pragma unroll
    for (int o = 16; o; o >>= 1) {
        lp += __shfl_down_sync(0xffffffffu, lp, o);
        ln += __shfl_down_sync(0xffffffffu, ln, o);
    }
    if ((tid & 31) == 0) { sred[0][tid >> 5] = lp; sred[1][tid >> 5] = ln; }
    __syncthreads();
    if (tid == 0) {
        double lpt = 0.0, lnt = 0.0;
#pragma unroll
        for (int i = 0; i < 8; ++i) { lpt += sred[0][i]; lnt += sred[1][i]; }
        const double recon = g_mse_total / (double)NEL;            // mean1 + mean2 combined
        const double lossP = 1.5 * (lpt / (double)BZ);
        const double lossN = 0.5 * (lnt / (double)(BZ * (BZ - 1)));
        out[0] = (float)(recon + lossP + lossN);
    }
}

extern "C" void kernel_launch(void* const* d_in, const int* in_sizes, int n_in,
                              void* d_out, int out_size)
{
    const float* o1 = (const float*)d_in[0];
    const float* z1 = (const float*)d_in[1];
    const float* o2 = (const float*)d_in[2];
    const float* z2 = (const float*)d_in[3];
    const float* i1 = (const float*)d_in[4];
    const float* i2 = (const float*)d_in[5];

    fused_kernel<<<TOTAL_BLOCKS, 256>>>(o1, z1, o2, z2, i1, i2);
    rowreduce_kernel<<<65, 256>>>(z1, z2);
    finalize_kernel<<<1, 256>>>((float*)d_out);
}

// round 15
// speedup vs baseline: 1.3599x; 1.3599x over previous
#include <cuda_runtime.h>

// Problem constants (fixed shapes from reference):
//   outputs1/2, input1/2 : [64,3,256,256] f32  -> NEL = 12,582,912 each
//   z1/z2                : [64,64,16,16]  f32  -> [64, 16384] flattened
#define BZ 64
#define DZ 16384
#define NEL 12582912
#define N4 (NEL / 4)

#define NCTR_BLOCKS 64          // contrastive blocks, each owns a 256-wide D slice
#define NMSE_BLOCKS 512         // 512 * 256 * 24 == N4 exactly
#define MSE_ITERS 24
#define NSQ_BLOCKS 16           // 16 blocks x 8 warps = 128 (row,tensor) sum-of-squares entries
#define TOTAL_BLOCKS (NCTR_BLOCKS + NMSE_BLOCKS + NSQ_BLOCKS)   // 592 = 4 CTAs/SM * 148 -> one wave

// Deterministic scratch (no atomics, every slot rewritten every launch)
__device__ float  g_crossp[NCTR_BLOCKS * 64 * 64];  // per-block partial cross[m][n]
__device__ float  g_sq[128];                        // COMPLETE row sums of squares (z1: 0..63, z2: 64..127)
__device__ double g_msep[NMSE_BLOCKS];              // per-block MSE partial sums
__device__ double g_mse_total;                      // fully reduced MSE sum
__device__ double g_row_lp[64];                     // per-row positive-margin term
__device__ double g_row_ln[64];                     // per-row negative-margin sum

__global__ __launch_bounds__(256)
void fused_kernel(const float* __restrict__ o1, const float* __restrict__ z1,
                  const float* __restrict__ o2, const float* __restrict__ z2,
                  const float* __restrict__ i1, const float* __restrict__ i2)
{
    const int tid = threadIdx.x;
    const int b   = blockIdx.x;

    if (b < NCTR_BLOCKS) {
        // ---------- contrastive cross-matrix partial: D slice [b*256, b*256+256) ----------
        // Shared tiles stored k-major: s[k][row], row padded to 68 (68*4 = 272 = 17*16,
        // so &s[k][4*t] stays 16B aligned for LDS.128 on the compute side).
        __shared__ __align__(16) float s1[32][68];
        __shared__ __align__(16) float s2[32][68];

        float acc[4][4];
#pragma unroll
        for (int i = 0; i < 4; ++i)
#pragma unroll
            for (int j = 0; j < 4; ++j) acc[i][j] = 0.0f;

        const int tx = tid & 15;   // n-tile coordinate
        const int ty = tid >> 4;   // m-tile coordinate
        const int c0 = b * 256;

        for (int t = 0; t < 8; ++t) {          // 8 k-tiles of 32
            const int ck = c0 + t * 32;
            __syncthreads();
            // load 64 rows x 32 k each tensor: 512 float4 per tensor, 2 per thread
#pragma unroll
            for (int i = 0; i < 2; ++i) {
                const int idx = tid + i * 256;      // 0..511
                const int r   = idx >> 3;           // row 0..63
                const int kk  = (idx & 7) * 4;      // k within tile
                float4 v1 = *(const float4*)(z1 + r * DZ + ck + kk);
                float4 v2 = *(const float4*)(z2 + r * DZ + ck + kk);
                s1[kk + 0][r] = v1.x; s1[kk + 1][r] = v1.y;
                s1[kk + 2][r] = v1.z; s1[kk + 3][r] = v1.w;
                s2[kk + 0][r] = v2.x; s2[kk + 1][r] = v2.y;
                s2[kk + 2][r] = v2.z; s2[kk + 3][r] = v2.w;
            }
            __syncthreads();
#pragma unroll
            for (int k = 0; k < 32; ++k) {
                const float4 av = *(const float4*)&s1[k][ty * 4];
                const float4 bv = *(const float4*)&s2[k][tx * 4];
                const float a[4] = {av.x, av.y, av.z, av.w};
                const float c[4] = {bv.x, bv.y, bv.z, bv.w};
#pragma unroll
                for (int i = 0; i < 4; ++i)
#pragma unroll
                    for (int j = 0; j < 4; ++j) acc[i][j] += a[i] * c[j];
            }
        }

        float* outp = g_crossp + b * 4096;
#pragma unroll
        for (int i = 0; i < 4; ++i)
#pragma unroll
            for (int j = 0; j < 4; ++j)
                outp[(ty * 4 + i) * 64 + (tx * 4 + j)] = acc[i][j];
    } else if (b < NCTR_BLOCKS + NMSE_BLOCKS) {
        // ---------- MSE: fixed 24 iters; pair 2 block-staggered by half the array ----------
        // Block mb reads pair 1 at chunk mb and pair 2 at chunk (mb+256)&511, so the
        // four 2MB-aligned streams never hit the same L2-slice/channel phase together.
        const int mb    = b - NCTR_BLOCKS;
        const int mb2   = (mb + 256) & 511;
        const int base  = mb  * (MSE_ITERS * 256) + tid;
        const int base2 = mb2 * (MSE_ITERS * 256) + tid;
        const float4* a1 = (const float4*)o1;
        const float4* c1 = (const float4*)i1;
        const float4* a2 = (const float4*)o2;
        const float4* c2 = (const float4*)i2;
        float s0 = 0.0f, s1s = 0.0f;
#pragma unroll
        for (int it = 0; it < MSE_ITERS; it += 2) {
            const int i0  = base  + it * 256;
            const int i1i = i0 + 256;
            const int j0  = base2 + it * 256;
            const int j1  = j0 + 256;
            const float4 xa = __ldcs(a1 + i0);
            const float4 ya = __ldcs(c1 + i0);
            const float4 xb = __ldcs(a2 + j0);
            const float4 yb = __ldcs(c2 + j0);
            const float4 xc = __ldcs(a1 + i1i);
            const float4 yc = __ldcs(c1 + i1i);
            const float4 xd = __ldcs(a2 + j1);
            const float4 yd = __ldcs(c2 + j1);
            float dx, dy, dz, dw;
            dx = xa.x - ya.x; dy = xa.y - ya.y; dz = xa.z - ya.z; dw = xa.w - ya.w;
            s0 += dx * dx + dy * dy + dz * dz + dw * dw;
            dx = xb.x - yb.x; dy = xb.y - yb.y; dz = xb.z - yb.z; dw = xb.w - yb.w;
            s0 += dx * dx + dy * dy + dz * dz + dw * dw;
            dx = xc.x - yc.x; dy = xc.y - yc.y; dz = xc.z - yc.z; dw = xc.w - yc.w;
            s1s += dx * dx + dy * dy + dz * dz + dw * dw;
            dx = xd.x - yd.x; dy = xd.y - yd.y; dz = xd.z - yd.z; dw = xd.w - yd.w;
            s1s += dx * dx + dy * dy + dz * dz + dw * dw;
        }
        float sum = s0 + s1s;
        __shared__ float red[8];
#pragma unroll
        for (int off = 16; off; off >>= 1) sum += __shfl_down_sync(0xffffffffu, sum, off);
        if ((tid & 31) == 0) red[tid >> 5] = sum;
        __syncthreads();
        if (tid < 32) {
            float v = (tid < 8) ? red[tid] : 0.0f;
#pragma unroll
            for (int off = 4; off; off >>= 1) v += __shfl_down_sync(0xffffffffu, v, off);
            if (tid == 0) g_msep[mb] = (double)v;
        }
    } else {
        // ---------- sum of squares: warp w of block bsq owns entry bsq*8+w ----------
        // entry e: e<64 -> z1 row e; else z2 row e-64. 32 lanes x 128 float4, 8
        // independent accumulators for full MLP. Runs inside the BW-bound wave.
        const int e    = (b - NCTR_BLOCKS - NMSE_BLOCKS) * 8 + (tid >> 5);
        const int lane = tid & 31;
        const float*  zp = (e < 64) ? (z1 + e * DZ) : (z2 + (e - 64) * DZ);
        const float4* zr = (const float4*)zp;
        float acc[8];
#pragma unroll
        for (int j = 0; j < 8; ++j) acc[j] = 0.0f;
        for (int i = 0; i < 128; i += 8) {
#pragma unroll
            for (int j = 0; j < 8; ++j) {
                const float4 v = zr[lane + (i + j) * 32];
                acc[j] += v.x * v.x + v.y * v.y + v.z * v.z + v.w * v.w;
            }
        }
        float s = ((acc[0] + acc[1]) + (acc[2] + acc[3]))
                + ((acc[4] + acc[5]) + (acc[6] + acc[7]));
#pragma unroll
        for (int o = 16; o; o >>= 1) s += __shfl_down_sync(0xffffffffu, s, o);
        if (lane == 0) g_sq[e] = s;
    }
}

// Blocks 0..63: reduce cross row m over the 64 partials + apply margins (g_sq ready).
// Block 64: reduce the MSE partials.
__global__ __launch_bounds__(256)
void rowreduce_kernel()
{
    const int tid = threadIdx.x;

    if (blockIdx.x == 64) {
        __shared__ double mred[8];
        double msum = 0.0;
#pragma unroll
        for (int i = tid; i < NMSE_BLOCKS; i += 256) msum += g_msep[i];
#pragma unroll
        for (int o = 16; o; o >>= 1) msum += __shfl_down_sync(0xffffffffu, msum, o);
        if ((tid & 31) == 0) mred[tid >> 5] = msum;
        __syncthreads();
        if (tid == 0) {
            double t = 0.0;
#pragma unroll
            for (int i = 0; i < 8; ++i) t += mred[i];
            g_mse_total = t;
        }
        return;
    }

    const int m = blockIdx.x;
    __shared__ float sq_sm[128];
    if (tid < 128) sq_sm[tid] = g_sq[tid];

    // reduce cross row m over the 64 partials
    const int n = tid & 63;       // output column
    const int q = tid >> 6;       // partial group 0..3 (16 partials each)
    float s = 0.0f;
#pragma unroll
    for (int j = 0; j < 16; ++j)
        s += g_crossp[(q * 16 + j) * 4096 + m * 64 + n];

    __shared__ float sm[4][64];
    __shared__ double dred[2];
    sm[q][n] = s;
    __syncthreads();

    if (tid < 64) {
        const float cr = sm[0][tid] + sm[1][tid] + sm[2][tid] + sm[3][tid];
        const double d = ((double)sq_sm[m] + (double)sq_sm[64 + tid] - 2.0 * (double)cr)
                         * (1.0 / (double)DZ);
        double lp = 0.0, ln = 0.0;
        if (m == tid) {
            if (d > 0.01) lp = d - 0.01;
        } else if (d < 0.4) {
            ln = 0.4 - d;
        }
#pragma unroll
        for (int o = 16; o; o >>= 1) {
            lp += __shfl_down_sync(0xffffffffu, lp, o);
            ln += __shfl_down_sync(0xffffffffu, ln, o);
        }
        if ((tid & 31) == 0) dred[tid >> 5] = ln + lp;   // lp folded in (only one warp has it)
        __syncthreads();
        if (tid == 0) {
            // separate lp exactly: recompute diagonal term directly (cheap, deterministic)
            const double dd = ((double)sq_sm[m] + (double)sq_sm[64 + m]
                               - 2.0 * (double)(sm[0][m] + sm[1][m] + sm[2][m] + sm[3][m]))
                              * (1.0 / (double)DZ);
            const double lpv = (dd > 0.01) ? (dd - 0.01) : 0.0;
            g_row_lp[m] = lpv;
            g_row_ln[m] = dred[0] + dred[1] - lpv;
        }
    }
}

__device__ __forceinline__ double warp_red_d(double v)
{
#pragma unroll
    for (int o = 16; o; o >>= 1) v += __shfl_down_sync(0xffffffffu, v, o);
    return v;
}

__global__ __launch_bounds__(64)
void finalize_kernel(float* __restrict__ out)
{
    const int tid = threadIdx.x;
    __shared__ double sred[2][2];

    const double lp = g_row_lp[tid];
    const double ln = g_row_ln[tid];
    const double r1 = warp_red_d(lp);
    const double r2 = warp_red_d(ln);
    if ((tid & 31) == 0) { sred[0][tid >> 5] = r1; sred[1][tid >> 5] = r2; }
    __syncthreads();
    if (tid == 0) {
        const double recon = g_mse_total / (double)NEL;            // mean1 + mean2 combined
        const double lossP = 1.5 * ((sred[0][0] + sred[0][1]) / (double)BZ);
        const double lossN = 0.5 * ((sred[1][0] + sred[1][1]) / (double)(BZ * (BZ - 1)));
        out[0] = (float)(recon + lossP + lossN);
    }
}

extern "C" void kernel_launch(void* const* d_in, const int* in_sizes, int n_in,
                              void* d_out, int out_size)
{
    const float* o1 = (const float*)d_in[0];
    const float* z1 = (const float*)d_in[1];
    const float* o2 = (const float*)d_in[2];
    const float* z2 = (const float*)d_in[3];
    const float* i1 = (const float*)d_in[4];
    const float* i2 = (const float*)d_in[5];

    fused_kernel<<<TOTAL_BLOCKS, 256>>>(o1, z1, o2, z2, i1, i2);
    rowreduce_kernel<<<65, 256>>>();
    finalize_kernel<<<1, 64>>>((float*)d_out);
}

// round 17
// speedup vs baseline: 1.4140x; 1.0398x over previous
#include <cuda_runtime.h>

// Problem constants (fixed shapes from reference):
//   outputs1/2, input1/2 : [64,3,256,256] f32  -> NEL = 12,582,912 each
//   z1/z2                : [64,64,16,16]  f32  -> [64, 16384] flattened
#define BZ 64
#define DZ 16384
#define NEL 12582912
#define N4 (NEL / 4)

#define NCTR_BLOCKS 64          // contrastive blocks, each owns a 256-wide D slice
#define NMSE_BLOCKS 512         // 512 * 256 * 24 == N4 exactly
#define MSE_ITERS 24
#define NSQ_BLOCKS 16           // 16 blocks x 8 warps = 128 (row,tensor) sum-of-squares entries
#define TOTAL_BLOCKS (NCTR_BLOCKS + NMSE_BLOCKS + NSQ_BLOCKS)   // 592 = 4 CTAs/SM * 148 -> one wave

// Deterministic scratch (no atomics, every slot rewritten every launch)
__device__ float  g_crossp[NCTR_BLOCKS * 64 * 64];  // per-block partial cross[m][n]
__device__ float  g_sq[128];                        // COMPLETE row sums of squares (z1: 0..63, z2: 64..127)
__device__ double g_msep[NMSE_BLOCKS];              // per-block MSE partial sums
__device__ double g_mse_total;                      // fully reduced MSE sum
__device__ double g_row_lp[64];                     // per-row positive-margin term
__device__ double g_row_ln[64];                     // per-row negative-margin sum

__global__ __launch_bounds__(256)
void fused_kernel(const float* __restrict__ o1, const float* __restrict__ z1,
                  const float* __restrict__ o2, const float* __restrict__ z2,
                  const float* __restrict__ i1, const float* __restrict__ i2)
{
    const int tid = threadIdx.x;
    const int b   = blockIdx.x;

    if (b < NCTR_BLOCKS) {
        // ---------- contrastive cross-matrix partial: D slice [b*256, b*256+256) ----------
        // Shared tiles stored k-major: s[k][row], row padded to 68 (68*4 = 272 = 17*16,
        // so &s[k][4*t] stays 16B aligned for LDS.128 on the compute side).
        __shared__ __align__(16) float s1[32][68];
        __shared__ __align__(16) float s2[32][68];

        float acc[4][4];
#pragma unroll
        for (int i = 0; i < 4; ++i)
#pragma unroll
            for (int j = 0; j < 4; ++j) acc[i][j] = 0.0f;

        const int tx = tid & 15;   // n-tile coordinate
        const int ty = tid >> 4;   // m-tile coordinate
        const int c0 = b * 256;

        for (int t = 0; t < 8; ++t) {          // 8 k-tiles of 32
            const int ck = c0 + t * 32;
            __syncthreads();
            // load 64 rows x 32 k each tensor: 512 float4 per tensor, 2 per thread
#pragma unroll
            for (int i = 0; i < 2; ++i) {
                const int idx = tid + i * 256;      // 0..511
                const int r   = idx >> 3;           // row 0..63
                const int kk  = (idx & 7) * 4;      // k within tile
                float4 v1 = *(const float4*)(z1 + r * DZ + ck + kk);
                float4 v2 = *(const float4*)(z2 + r * DZ + ck + kk);
                s1[kk + 0][r] = v1.x; s1[kk + 1][r] = v1.y;
                s1[kk + 2][r] = v1.z; s1[kk + 3][r] = v1.w;
                s2[kk + 0][r] = v2.x; s2[kk + 1][r] = v2.y;
                s2[kk + 2][r] = v2.z; s2[kk + 3][r] = v2.w;
            }
            __syncthreads();
#pragma unroll
            for (int k = 0; k < 32; ++k) {
                const float4 av = *(const float4*)&s1[k][ty * 4];
                const float4 bv = *(const float4*)&s2[k][tx * 4];
                const float a[4] = {av.x, av.y, av.z, av.w};
                const float c[4] = {bv.x, bv.y, bv.z, bv.w};
#pragma unroll
                for (int i = 0; i < 4; ++i)
#pragma unroll
                    for (int j = 0; j < 4; ++j) acc[i][j] += a[i] * c[j];
            }
        }

        float* outp = g_crossp + b * 4096;
#pragma unroll
        for (int i = 0; i < 4; ++i)
#pragma unroll
            for (int j = 0; j < 4; ++j)
                outp[(ty * 4 + i) * 64 + (tx * 4 + j)] = acc[i][j];
    } else if (b < NCTR_BLOCKS + NMSE_BLOCKS) {
        // ---------- MSE: fixed 24 iters; pair 2 block-staggered by half the array ----------
        // Block mb reads pair 1 at chunk mb and pair 2 at chunk (mb+256)&511, so the
        // four 2MB-aligned streams never hit the same L2-slice/channel phase together.
        const int mb    = b - NCTR_BLOCKS;
        const int mb2   = (mb + 256) & 511;
        const int base  = mb  * (MSE_ITERS * 256) + tid;
        const int base2 = mb2 * (MSE_ITERS * 256) + tid;
        const float4* a1 = (const float4*)o1;
        const float4* c1 = (const float4*)i1;
        const float4* a2 = (const float4*)o2;
        const float4* c2 = (const float4*)i2;
        float s0 = 0.0f, s1s = 0.0f;
#pragma unroll
        for (int it = 0; it < MSE_ITERS; it += 2) {
            const int i0  = base  + it * 256;
            const int i1i = i0 + 256;
            const int j0  = base2 + it * 256;
            const int j1  = j0 + 256;
            const float4 xa = __ldcs(a1 + i0);
            const float4 ya = __ldcs(c1 + i0);
            const float4 xb = __ldcs(a2 + j0);
            const float4 yb = __ldcs(c2 + j0);
            const float4 xc = __ldcs(a1 + i1i);
            const float4 yc = __ldcs(c1 + i1i);
            const float4 xd = __ldcs(a2 + j1);
            const float4 yd = __ldcs(c2 + j1);
            float dx, dy, dz, dw;
            dx = xa.x - ya.x; dy = xa.y - ya.y; dz = xa.z - ya.z; dw = xa.w - ya.w;
            s0 += dx * dx + dy * dy + dz * dz + dw * dw;
            dx = xb.x - yb.x; dy = xb.y - yb.y; dz = xb.z - yb.z; dw = xb.w - yb.w;
            s0 += dx * dx + dy * dy + dz * dz + dw * dw;
            dx = xc.x - yc.x; dy = xc.y - yc.y; dz = xc.z - yc.z; dw = xc.w - yc.w;
            s1s += dx * dx + dy * dy + dz * dz + dw * dw;
            dx = xd.x - yd.x; dy = xd.y - yd.y; dz = xd.z - yd.z; dw = xd.w - yd.w;
            s1s += dx * dx + dy * dy + dz * dz + dw * dw;
        }
        float sum = s0 + s1s;
        __shared__ float red[8];
#pragma unroll
        for (int off = 16; off; off >>= 1) sum += __shfl_down_sync(0xffffffffu, sum, off);
        if ((tid & 31) == 0) red[tid >> 5] = sum;
        __syncthreads();
        if (tid < 32) {
            float v = (tid < 8) ? red[tid] : 0.0f;
#pragma unroll
            for (int off = 4; off; off >>= 1) v += __shfl_down_sync(0xffffffffu, v, off);
            if (tid == 0) g_msep[mb] = (double)v;
        }
    } else {
        // ---------- sum of squares: warp w of block bsq owns entry bsq*8+w ----------
        // entry e: e<64 -> z1 row e; else z2 row e-64. 32 lanes x 128 float4, 8
        // independent accumulators for full MLP. Runs inside the BW-bound wave.
        const int e    = (b - NCTR_BLOCKS - NMSE_BLOCKS) * 8 + (tid >> 5);
        const int lane = tid & 31;
        const float*  zp = (e < 64) ? (z1 + e * DZ) : (z2 + (e - 64) * DZ);
        const float4* zr = (const float4*)zp;
        float acc[8];
#pragma unroll
        for (int j = 0; j < 8; ++j) acc[j] = 0.0f;
        for (int i = 0; i < 128; i += 8) {
#pragma unroll
            for (int j = 0; j < 8; ++j) {
                const float4 v = zr[lane + (i + j) * 32];
                acc[j] += v.x * v.x + v.y * v.y + v.z * v.z + v.w * v.w;
            }
        }
        float s = ((acc[0] + acc[1]) + (acc[2] + acc[3]))
                + ((acc[4] + acc[5]) + (acc[6] + acc[7]));
#pragma unroll
        for (int o = 16; o; o >>= 1) s += __shfl_down_sync(0xffffffffu, s, o);
        if (lane == 0) g_sq[e] = s;
    }
}

// Blocks 0..63: reduce cross row m over the 64 partials + apply margins (g_sq ready).
// Block 64: reduce the MSE partials.
// PDL: launched with ProgrammaticStreamSerialization; waits on the producer grid
// via cudaGridDependencySynchronize() before reading any of its output.
__global__ __launch_bounds__(256)
void rowreduce_kernel()
{
    const int tid = threadIdx.x;

    cudaGridDependencySynchronize();   // fused_kernel results visible after this

    if (blockIdx.x == 64) {
        __shared__ double mred[8];
        double msum = 0.0;
#pragma unroll
        for (int i = tid; i < NMSE_BLOCKS; i += 256) msum += g_msep[i];
#pragma unroll
        for (int o = 16; o; o >>= 1) msum += __shfl_down_sync(0xffffffffu, msum, o);
        if ((tid & 31) == 0) mred[tid >> 5] = msum;
        __syncthreads();
        if (tid == 0) {
            double t = 0.0;
#pragma unroll
            for (int i = 0; i < 8; ++i) t += mred[i];
            g_mse_total = t;
        }
        return;
    }

    const int m = blockIdx.x;
    __shared__ float sq_sm[128];
    if (tid < 128) sq_sm[tid] = g_sq[tid];

    // reduce cross row m over the 64 partials
    const int n = tid & 63;       // output column
    const int q = tid >> 6;       // partial group 0..3 (16 partials each)
    float s = 0.0f;
#pragma unroll
    for (int j = 0; j < 16; ++j)
        s += g_crossp[(q * 16 + j) * 4096 + m * 64 + n];

    __shared__ float sm[4][64];
    __shared__ double dred[2];
    sm[q][n] = s;
    __syncthreads();

    if (tid < 64) {
        const float cr = sm[0][tid] + sm[1][tid] + sm[2][tid] + sm[3][tid];
        const double d = ((double)sq_sm[m] + (double)sq_sm[64 + tid] - 2.0 * (double)cr)
                         * (1.0 / (double)DZ);
        double lp = 0.0, ln = 0.0;
        if (m == tid) {
            if (d > 0.01) lp = d - 0.01;
        } else if (d < 0.4) {
            ln = 0.4 - d;
        }
#pragma unroll
        for (int o = 16; o; o >>= 1) {
            lp += __shfl_down_sync(0xffffffffu, lp, o);
            ln += __shfl_down_sync(0xffffffffu, ln, o);
        }
        if ((tid & 31) == 0) dred[tid >> 5] = ln + lp;   // lp folded in (only one warp has it)
        __syncthreads();
        if (tid == 0) {
            // separate lp exactly: recompute diagonal term directly (cheap, deterministic)
            const double dd = ((double)sq_sm[m] + (double)sq_sm[64 + m]
                               - 2.0 * (double)(sm[0][m] + sm[1][m] + sm[2][m] + sm[3][m]))
                              * (1.0 / (double)DZ);
            const double lpv = (dd > 0.01) ? (dd - 0.01) : 0.0;
            g_row_lp[m] = lpv;
            g_row_ln[m] = dred[0] + dred[1] - lpv;
        }
    }
}

__device__ __forceinline__ double warp_red_d(double v)
{
#pragma unroll
    for (int o = 16; o; o >>= 1) v += __shfl_down_sync(0xffffffffu, v, o);
    return v;
}

__global__ __launch_bounds__(64)
void finalize_kernel(float* __restrict__ out)
{
    const int tid = threadIdx.x;
    __shared__ double sred[2][2];

    cudaGridDependencySynchronize();   // rowreduce_kernel results visible after this

    const double lp = g_row_lp[tid];
    const double ln = g_row_ln[tid];
    const double r1 = warp_red_d(lp);
    const double r2 = warp_red_d(ln);
    if ((tid & 31) == 0) { sred[0][tid >> 5] = r1; sred[1][tid >> 5] = r2; }
    __syncthreads();
    if (tid == 0) {
        const double recon = g_mse_total / (double)NEL;            // mean1 + mean2 combined
        const double lossP = 1.5 * ((sred[0][0] + sred[0][1]) / (double)BZ);
        const double lossN = 0.5 * ((sred[1][0] + sred[1][1]) / (double)(BZ * (BZ - 1)));
        out[0] = (float)(recon + lossP + lossN);
    }
}

extern "C" void kernel_launch(void* const* d_in, const int* in_sizes, int n_in,
                              void* d_out, int out_size)
{
    const float* o1 = (const float*)d_in[0];
    const float* z1 = (const float*)d_in[1];
    const float* o2 = (const float*)d_in[2];
    const float* z2 = (const float*)d_in[3];
    const float* i1 = (const float*)d_in[4];
    const float* i2 = (const float*)d_in[5];

    fused_kernel<<<TOTAL_BLOCKS, 256>>>(o1, z1, o2, z2, i1, i2);

    // Tail kernels launched with Programmatic Dependent Launch so their grid
    // setup overlaps the predecessor's execution; each kernel begins with
    // cudaGridDependencySynchronize() before consuming producer data.
    cudaLaunchAttribute attr[1];
    attr[0].id = cudaLaunchAttributeProgrammaticStreamSerialization;
    attr[0].val.programmaticStreamSerializationAllowed = 1;

    {
        cudaLaunchConfig_t cfg = {};
        cfg.gridDim  = dim3(65, 1, 1);
        cfg.blockDim = dim3(256, 1, 1);
        cfg.attrs    = attr;
        cfg.numAttrs = 1;
        cudaLaunchKernelEx(&cfg, rowreduce_kernel);
    }
    {
        cudaLaunchConfig_t cfg = {};
        cfg.gridDim  = dim3(1, 1, 1);
        cfg.blockDim = dim3(64, 1, 1);
        cfg.attrs    = attr;
        cfg.numAttrs = 1;
        cudaLaunchKernelEx(&cfg, finalize_kernel, (float*)d_out);
    }
}